// round 6
// baseline (speedup 1.0000x reference)
#include <cuda_runtime.h>
#include <cuda_bf16.h>
#include <cstdint>
#include <cstddef>

#define K_DIM  4096
#define M_ROWS 8192
#define N_DIM  4096
#define KQ_DIM 3968            // exact-bf16 integer-weight part
#define N_OUTL 128

// GEMM tiling
#define TM 256
#define TN 128
#define KC 32
#define NT (K_DIM / KC)        // 128 k-iterations
#define NQ_IT (KQ_DIM / KC)    // 124 q-part iterations
#define STAGES 4

// Stage smem layout (bytes)
#define OFF_AH 0
#define OFF_AL (16 * 1024)
#define OFF_BH (32 * 1024)
#define OFF_BL (40 * 1024)
#define STAGE_BYTES (48 * 1024)
#define SMEM_TOTAL (STAGES * STAGE_BYTES)   // 196608

// ---------------------------------------------------------------------------
// Device-global scratch (no runtime allocation)
// ---------------------------------------------------------------------------
__device__ __nv_bfloat16 g_Ahi[(size_t)M_ROWS * K_DIM];   // permuted x, hi
__device__ __nv_bfloat16 g_Alo[(size_t)M_ROWS * K_DIM];   // permuted x, lo
__device__ __nv_bfloat16 g_Qb [(size_t)N_DIM * KQ_DIM];   // exact bf16 int weights
__device__ __nv_bfloat16 g_FPh[(size_t)N_DIM * N_OUTL];
__device__ __nv_bfloat16 g_FPl[(size_t)N_DIM * N_OUTL];

// ---------------------------------------------------------------------------
// Base-target PTX helpers (no sm_103a-gated instructions)
// ---------------------------------------------------------------------------
__device__ __forceinline__ uint32_t smem_to_u32(const void* p) {
    uint32_t a;
    asm("{ .reg .u64 t; cvta.to.shared.u64 t, %1; cvt.u32.u64 %0, t; }"
        : "=r"(a) : "l"(p));
    return a;
}

__device__ __forceinline__ void cpa16(uint32_t dst, const void* src) {
    asm volatile("cp.async.cg.shared.global [%0], [%1], 16;"
                 :: "r"(dst), "l"(src) : "memory");
}

__device__ __forceinline__ void ldsm4(uint32_t* r, uint32_t addr) {
    asm volatile("ldmatrix.sync.aligned.m8n8.x4.shared.b16 {%0,%1,%2,%3}, [%4];"
                 : "=r"(r[0]), "=r"(r[1]), "=r"(r[2]), "=r"(r[3]) : "r"(addr));
}

__device__ __forceinline__ void mma16816(float* c, const uint32_t* a,
                                         uint32_t b0, uint32_t b1) {
    asm volatile(
        "mma.sync.aligned.m16n8k16.row.col.f32.bf16.bf16.f32 "
        "{%0,%1,%2,%3}, {%4,%5,%6,%7}, {%8,%9}, {%0,%1,%2,%3};"
        : "+f"(c[0]), "+f"(c[1]), "+f"(c[2]), "+f"(c[3])
        : "r"(a[0]), "r"(a[1]), "r"(a[2]), "r"(a[3]), "r"(b0), "r"(b1));
}

// Conflict-free tile layout (verified): rows of 32 bf16 (64B), 2 rows per
// 128B line, 16B granule XOR-swizzled by line index.
__device__ __forceinline__ uint32_t tile_off(int row, int g) {
    int p = row >> 1;
    return (uint32_t)(p * 128 + (row & 1) * 64 + ((g ^ (p & 3)) * 16));
}

// ---------------------------------------------------------------------------
// Prep A: permute columns of x (xp[invp[c]] = x[c]) and split fp32 -> bf16
// hi/lo. One CTA per row; smem staging keeps reads AND writes coalesced.
// ---------------------------------------------------------------------------
__global__ __launch_bounds__(256)
void perm_split_A_kernel(const float* __restrict__ x,
                         const int* __restrict__ invp) {
    __shared__ float rs[K_DIM];
    const int m = blockIdx.x;
    const float* xr = x + (size_t)m * K_DIM;
    for (int j = threadIdx.x; j < K_DIM; j += 256)
        rs[invp[j]] = xr[j];                        // smem scatter
    __syncthreads();
    __nv_bfloat162* H = (__nv_bfloat162*)(g_Ahi + (size_t)m * K_DIM);
    __nv_bfloat162* L = (__nv_bfloat162*)(g_Alo + (size_t)m * K_DIM);
    for (int j2 = threadIdx.x; j2 < K_DIM / 2; j2 += 256) {
        float v0 = rs[2 * j2], v1 = rs[2 * j2 + 1];
        __nv_bfloat16 h0 = __float2bfloat16(v0), h1 = __float2bfloat16(v1);
        __nv_bfloat16 l0 = __float2bfloat16(v0 - __bfloat162float(h0));
        __nv_bfloat16 l1 = __float2bfloat16(v1 - __bfloat162float(h1));
        H[j2] = __halves2bfloat162(h0, h1);
        L[j2] = __halves2bfloat162(l0, l1);
    }
}

// Prep W: exact bf16 copy of integer q_weight (NO alpha), hi/lo split of fp_w.
__global__ void prep_Q_kernel(const float* __restrict__ qw) {
    size_t idx = (size_t)blockIdx.x * 256 + threadIdx.x;   // O*KQ_DIM
    g_Qb[idx] = __float2bfloat16(qw[idx]);                 // exact: ints in [-8,7]
}

__global__ void prep_FP_kernel(const float* __restrict__ fw) {
    size_t idx = (size_t)blockIdx.x * 256 + threadIdx.x;   // O*N_OUTL
    float v = fw[idx];
    __nv_bfloat16 h = __float2bfloat16(v);
    g_FPh[idx] = h;
    g_FPl[idx] = __float2bfloat16(v - __bfloat162float(h));
}

// ---------------------------------------------------------------------------
// GEMM: acc = xp[:, :3968] * q^T (2-term), acc *= alpha, acc += outliers
// (3-term), C = acc + bias.
// CTA 256x128, 512 threads / 16 warps (4m x 4n), warp tile 64x32,
// 4-stage cp.async pipeline.
// ---------------------------------------------------------------------------
__global__ __launch_bounds__(512, 1)
void gemm_hmma_kernel(const float* __restrict__ alpha,
                      const float* __restrict__ bias,
                      float* __restrict__ C) {
    extern __shared__ char smem[];
    const uint32_t sbase = smem_to_u32(smem);
    const int tid = threadIdx.x;
    const int wid = tid >> 5;
    const int lid = tid & 31;
    const int wm  = wid >> 2;          // 0..3 -> m offset wm*64
    const int wn  = wid & 3;           // 0..3 -> n offset wn*32
    const int m0  = blockIdx.y * TM;
    const int n0  = blockIdx.x * TN;

    float acc[4][4][4];                // [m16 frag][n8 frag][quad]
    #pragma unroll
    for (int i = 0; i < 4; i++)
        #pragma unroll
        for (int j = 0; j < 4; j++)
            #pragma unroll
            for (int t = 0; t < 4; t++) acc[i][j][t] = 0.0f;

    // ---- stage loader: 512 threads, 5-6 cp.async each ----
    const int lrow = tid >> 2;          // 0..127
    const int lg   = tid & 3;           // 16B granule within 64B row
    auto load_stage = [&](int slot, int kt) {
        const uint32_t stg = sbase + slot * STAGE_BYTES;
        const int k0 = kt * KC;
        #pragma unroll
        for (int i = 0; i < 2; i++) {   // A: 256 rows
            int row = lrow + i * 128;
            uint32_t o = tile_off(row, lg);
            const size_t gsrc = (size_t)(m0 + row) * K_DIM + k0 + lg * 8;
            cpa16(stg + OFF_AH + o, g_Ahi + gsrc);
            cpa16(stg + OFF_AL + o, g_Alo + gsrc);
        }
        {
            uint32_t o = tile_off(lrow, lg);     // B: 128 rows
            if (kt < NQ_IT) {
                cpa16(stg + OFF_BH + o,
                      g_Qb + (size_t)(n0 + lrow) * KQ_DIM + k0 + lg * 8);
            } else {
                const int ko = k0 - KQ_DIM;      // 0,32,64,96
                const size_t gsrc = (size_t)(n0 + lrow) * N_OUTL + ko + lg * 8;
                cpa16(stg + OFF_BH + o, g_FPh + gsrc);
                cpa16(stg + OFF_BL + o, g_FPl + gsrc);
            }
        }
    };

    const int frow = lid & 15;
    const int fg   = lid >> 4;

    // q-part: 2 terms (xh*q + xl*q), B exact. 10 LDSM + 32 MMA per s-step.
    auto compute_q = [&](int slot) {
        const uint32_t stg = sbase + slot * STAGE_BYTES;
        #pragma unroll
        for (int s = 0; s < 2; s++) {
            uint32_t ah[4][4], al[4][4], bh[2][4];
            #pragma unroll
            for (int j = 0; j < 2; j++) {
                int row = wn * 32 + j * 16 + frow;
                ldsm4(bh[j], stg + OFF_BH + tile_off(row, 2 * s + fg));
            }
            #pragma unroll
            for (int i = 0; i < 4; i++) {
                int row = wm * 64 + i * 16 + frow;
                uint32_t o = tile_off(row, 2 * s + fg);
                ldsm4(ah[i], stg + OFF_AH + o);
                ldsm4(al[i], stg + OFF_AL + o);
            }
            #pragma unroll
            for (int i = 0; i < 4; i++)
                #pragma unroll
                for (int j = 0; j < 2; j++) {
                    mma16816(acc[i][2 * j],     ah[i], bh[j][0], bh[j][2]);
                    mma16816(acc[i][2 * j + 1], ah[i], bh[j][1], bh[j][3]);
                    mma16816(acc[i][2 * j],     al[i], bh[j][0], bh[j][2]);
                    mma16816(acc[i][2 * j + 1], al[i], bh[j][1], bh[j][3]);
                }
        }
    };

    // outlier part: 3 terms (ah*bh + al*bh + ah*bl). 12 LDSM + 48 MMA.
    auto compute_o = [&](int slot) {
        const uint32_t stg = sbase + slot * STAGE_BYTES;
        #pragma unroll
        for (int s = 0; s < 2; s++) {
            uint32_t ah[4][4], al[4][4], bh[2][4], bl[2][4];
            #pragma unroll
            for (int j = 0; j < 2; j++) {
                int row = wn * 32 + j * 16 + frow;
                uint32_t o = tile_off(row, 2 * s + fg);
                ldsm4(bh[j], stg + OFF_BH + o);
                ldsm4(bl[j], stg + OFF_BL + o);
            }
            #pragma unroll
            for (int i = 0; i < 4; i++) {
                int row = wm * 64 + i * 16 + frow;
                uint32_t o = tile_off(row, 2 * s + fg);
                ldsm4(ah[i], stg + OFF_AH + o);
                ldsm4(al[i], stg + OFF_AL + o);
            }
            #pragma unroll
            for (int i = 0; i < 4; i++)
                #pragma unroll
                for (int j = 0; j < 2; j++) {
                    mma16816(acc[i][2 * j],     ah[i], bh[j][0], bh[j][2]);
                    mma16816(acc[i][2 * j + 1], ah[i], bh[j][1], bh[j][3]);
                    mma16816(acc[i][2 * j],     al[i], bh[j][0], bh[j][2]);
                    mma16816(acc[i][2 * j + 1], al[i], bh[j][1], bh[j][3]);
                    mma16816(acc[i][2 * j],     ah[i], bl[j][0], bl[j][2]);
                    mma16816(acc[i][2 * j + 1], ah[i], bl[j][1], bl[j][3]);
                }
        }
    };

    const int tq = lid & 3;             // fragment col pair

    // ---- pipeline ----
    #pragma unroll
    for (int s = 0; s < STAGES - 1; s++) {
        load_stage(s, s);
        asm volatile("cp.async.commit_group;" ::: "memory");
    }
    for (int kt = 0; kt < NT; kt++) {
        asm volatile("cp.async.wait_group 2;" ::: "memory");
        __syncthreads();
        const int nx = kt + STAGES - 1;
        if (nx < NT) load_stage(nx & (STAGES - 1), nx);
        asm volatile("cp.async.commit_group;" ::: "memory");

        if (kt == NQ_IT) {
            // q-part done: apply per-output alpha to accumulators
            #pragma unroll
            for (int j2 = 0; j2 < 4; j2++) {
                const int nc = n0 + wn * 32 + j2 * 8 + 2 * tq;
                const float s0 = alpha[nc], s1 = alpha[nc + 1];
                #pragma unroll
                for (int i = 0; i < 4; i++) {
                    acc[i][j2][0] *= s0; acc[i][j2][1] *= s1;
                    acc[i][j2][2] *= s0; acc[i][j2][3] *= s1;
                }
            }
        }
        if (kt < NQ_IT) compute_q(kt & (STAGES - 1));
        else            compute_o(kt & (STAGES - 1));
    }

    // ---- epilogue: bias + float2 stores ----
    const int qid = lid >> 2;
    #pragma unroll
    for (int i = 0; i < 4; i++) {
        const int mrow = m0 + wm * 64 + i * 16 + qid;
        #pragma unroll
        for (int j2 = 0; j2 < 4; j2++) {
            const int nc = n0 + wn * 32 + j2 * 8 + 2 * tq;
            const float b0 = bias[nc], b1 = bias[nc + 1];
            float2 v0 = make_float2(acc[i][j2][0] + b0, acc[i][j2][1] + b1);
            float2 v1 = make_float2(acc[i][j2][2] + b0, acc[i][j2][3] + b1);
            *(float2*)&C[(size_t)mrow * N_DIM + nc]       = v0;
            *(float2*)&C[(size_t)(mrow + 8) * N_DIM + nc] = v1;
        }
    }
}

// ---------------------------------------------------------------------------
// Launch. Inputs: input, q_weight, fp_weight, alpha_scale, bias, inv_col_perm.
// ---------------------------------------------------------------------------
extern "C" void kernel_launch(void* const* d_in, const int* in_sizes, int n_in,
                              void* d_out, int out_size) {
    const float* input = (const float*)d_in[0];
    const float* qw    = (const float*)d_in[1];
    const float* fw    = (const float*)d_in[2];
    const float* alpha = (const float*)d_in[3];
    const float* bias  = (const float*)d_in[4];
    const int*   invp  = (const int*)  d_in[5];
    float* out = (float*)d_out;

    perm_split_A_kernel<<<M_ROWS, 256>>>(input, invp);
    prep_Q_kernel<<<(N_DIM * KQ_DIM) / 256, 256>>>(qw);
    prep_FP_kernel<<<(N_DIM * N_OUTL) / 256, 256>>>(fw);

    static bool attr_set = false;
    if (!attr_set) {
        cudaFuncSetAttribute(gemm_hmma_kernel,
                             cudaFuncAttributeMaxDynamicSharedMemorySize, SMEM_TOTAL);
        attr_set = true;
    }
    dim3 grid(N_DIM / TN, M_ROWS / TM);   // (32, 32)
    gemm_hmma_kernel<<<grid, 512, SMEM_TOTAL>>>(alpha, bias, out);
}

// round 7
// speedup vs baseline: 2.1422x; 2.1422x over previous
#include <cuda_runtime.h>
#include <cuda_fp16.h>
#include <cstdint>
#include <cstddef>

#define K_DIM  4096
#define M_ROWS 8192
#define N_DIM  4096
#define KQ_DIM 3968            // exact-fp16 integer-weight part
#define N_OUTL 128

// GEMM tiling
#define TM 256
#define TN 128
#define KC 64
#define NT (K_DIM / KC)        // 64 k-iterations
#define NQ_IT (KQ_DIM / KC)    // 62 q-part iterations
#define STAGES 4

// Stage smem layout (bytes): A 256x64 fp16 = 32K, B 128x64 fp16 = 16K
#define OFF_A 0
#define OFF_B (32 * 1024)
#define STAGE_BYTES (48 * 1024)
#define SMEM_TOTAL (STAGES * STAGE_BYTES)   // 196608

// ---------------------------------------------------------------------------
// Device-global scratch (no runtime allocation)
// ---------------------------------------------------------------------------
__device__ __half g_A [(size_t)M_ROWS * K_DIM];    // permuted x, fp16
__device__ __half g_Q [(size_t)N_DIM * KQ_DIM];    // exact fp16 int weights
__device__ __half g_FP[(size_t)N_DIM * N_OUTL];    // fp16 outlier weights

// ---------------------------------------------------------------------------
// Base-target PTX helpers
// ---------------------------------------------------------------------------
__device__ __forceinline__ uint32_t smem_to_u32(const void* p) {
    uint32_t a;
    asm("{ .reg .u64 t; cvta.to.shared.u64 t, %1; cvt.u32.u64 %0, t; }"
        : "=r"(a) : "l"(p));
    return a;
}

__device__ __forceinline__ void cpa16(uint32_t dst, const void* src) {
    asm volatile("cp.async.cg.shared.global [%0], [%1], 16;"
                 :: "r"(dst), "l"(src) : "memory");
}

__device__ __forceinline__ void ldsm4(uint32_t* r, uint32_t addr) {
    asm volatile("ldmatrix.sync.aligned.m8n8.x4.shared.b16 {%0,%1,%2,%3}, [%4];"
                 : "=r"(r[0]), "=r"(r[1]), "=r"(r[2]), "=r"(r[3]) : "r"(addr));
}

__device__ __forceinline__ void mma16816(float* c, const uint32_t* a,
                                         uint32_t b0, uint32_t b1) {
    asm volatile(
        "mma.sync.aligned.m16n8k16.row.col.f32.f16.f16.f32 "
        "{%0,%1,%2,%3}, {%4,%5,%6,%7}, {%8,%9}, {%0,%1,%2,%3};"
        : "+f"(c[0]), "+f"(c[1]), "+f"(c[2]), "+f"(c[3])
        : "r"(a[0]), "r"(a[1]), "r"(a[2]), "r"(a[3]), "r"(b0), "r"(b1));
}

// 128B-row tile, 8 granules of 16B, XOR-swizzled: any ldmatrix 8-lane phase
// (8 consecutive rows, fixed granule) covers all 32 banks.
__device__ __forceinline__ uint32_t tile_off(int row, int g) {
    return (uint32_t)(row * 128 + ((g ^ (row & 7)) * 16));
}

// ---------------------------------------------------------------------------
// Prep A: permute columns (xp[invp[c]] = x[c]) and convert fp32 -> fp16.
// One CTA per row; smem staging keeps reads AND writes coalesced.
// ---------------------------------------------------------------------------
__global__ __launch_bounds__(256)
void perm_conv_A_kernel(const float* __restrict__ x,
                        const int* __restrict__ invp) {
    __shared__ float rs[K_DIM];
    const int m = blockIdx.x;
    const float* xr = x + (size_t)m * K_DIM;
    for (int j = threadIdx.x; j < K_DIM; j += 256)
        rs[invp[j]] = xr[j];                        // smem scatter
    __syncthreads();
    __half2* H = (__half2*)(g_A + (size_t)m * K_DIM);
    for (int j2 = threadIdx.x; j2 < K_DIM / 2; j2 += 256)
        H[j2] = __floats2half2_rn(rs[2 * j2], rs[2 * j2 + 1]);
}

// exact fp16 copy of integer q_weight (ints in [-8,7])
__global__ void prep_Q_kernel(const float* __restrict__ qw) {
    size_t idx = (size_t)blockIdx.x * 256 + threadIdx.x;   // O*KQ_DIM
    g_Q[idx] = __float2half_rn(qw[idx]);
}

__global__ void prep_FP_kernel(const float* __restrict__ fw) {
    size_t idx = (size_t)blockIdx.x * 256 + threadIdx.x;   // O*N_OUTL
    g_FP[idx] = __float2half_rn(fw[idx]);
}

// ---------------------------------------------------------------------------
// GEMM: acc = xp[:, :3968] * q^T ; acc *= alpha[n] ; acc += outlier part ;
// C = acc + bias.  Single fp16 MMA term throughout.
// CTA 256x128, 256 threads / 8 warps (4m x 2n), warp tile 64x64,
// KC=64, 4-stage cp.async pipeline.
// ---------------------------------------------------------------------------
__global__ __launch_bounds__(256, 1)
void gemm_hmma_kernel(const float* __restrict__ alpha,
                      const float* __restrict__ bias,
                      float* __restrict__ C) {
    extern __shared__ char smem[];
    const uint32_t sbase = smem_to_u32(smem);
    const int tid = threadIdx.x;
    const int wid = tid >> 5;
    const int lid = tid & 31;
    const int wm  = wid >> 1;          // 0..3 -> m offset wm*64
    const int wn  = wid & 1;           // 0..1 -> n offset wn*64
    const int m0  = blockIdx.y * TM;
    const int n0  = blockIdx.x * TN;

    float acc[4][8][4];                // [m16][n8][quad]
    #pragma unroll
    for (int i = 0; i < 4; i++)
        #pragma unroll
        for (int j = 0; j < 8; j++)
            #pragma unroll
            for (int t = 0; t < 4; t++) acc[i][j][t] = 0.0f;

    // ---- stage loader: 12 cp.async x 16B per thread ----
    const int lrow = tid >> 3;          // 0..31
    const int lg   = tid & 7;           // granule 0..7 within 128B row
    auto load_stage = [&](int slot, int kt) {
        const uint32_t stg = sbase + slot * STAGE_BYTES;
        const int k0 = kt * KC;
        #pragma unroll
        for (int p = 0; p < 8; p++) {   // A: 256 rows
            int row = lrow + p * 32;
            cpa16(stg + OFF_A + tile_off(row, lg),
                  g_A + (size_t)(m0 + row) * K_DIM + k0 + lg * 8);
        }
        if (kt < NQ_IT) {
            #pragma unroll
            for (int p = 0; p < 4; p++) {   // B: 128 rows, exact int weights
                int row = lrow + p * 32;
                cpa16(stg + OFF_B + tile_off(row, lg),
                      g_Q + (size_t)(n0 + row) * KQ_DIM + k0 + lg * 8);
            }
        } else {
            const int ko = k0 - KQ_DIM;     // 0 or 64
            #pragma unroll
            for (int p = 0; p < 4; p++) {   // B: fp outlier weights
                int row = lrow + p * 32;
                cpa16(stg + OFF_B + tile_off(row, lg),
                      g_FP + (size_t)(n0 + row) * N_OUTL + ko + lg * 8);
            }
        }
    };

    const int frow = lid & 15;
    const int fg   = lid >> 4;

    // per stage: 4 k16 s-steps; per s-step 8 LDSM + 32 independent MMAs
    auto compute_stage = [&](int slot) {
        const uint32_t stg = sbase + slot * STAGE_BYTES;
        #pragma unroll
        for (int s = 0; s < 4; s++) {
            const int g = 2 * s + fg;
            uint32_t a[4][4], b[4][4];
            #pragma unroll
            for (int j = 0; j < 4; j++) {
                int row = wn * 64 + j * 16 + frow;
                ldsm4(b[j], stg + OFF_B + tile_off(row, g));
            }
            #pragma unroll
            for (int i = 0; i < 4; i++) {
                int row = wm * 64 + i * 16 + frow;
                ldsm4(a[i], stg + OFF_A + tile_off(row, g));
            }
            #pragma unroll
            for (int i = 0; i < 4; i++)
                #pragma unroll
                for (int j = 0; j < 4; j++) {
                    mma16816(acc[i][2 * j],     a[i], b[j][0], b[j][2]);
                    mma16816(acc[i][2 * j + 1], a[i], b[j][1], b[j][3]);
                }
        }
    };

    const int tq = lid & 3;             // fragment col pair

    // ---- pipeline ----
    #pragma unroll
    for (int s = 0; s < STAGES - 1; s++) {
        load_stage(s, s);
        asm volatile("cp.async.commit_group;" ::: "memory");
    }
    for (int kt = 0; kt < NT; kt++) {
        asm volatile("cp.async.wait_group 2;" ::: "memory");
        __syncthreads();
        const int nx = kt + STAGES - 1;
        if (nx < NT) load_stage(nx & (STAGES - 1), nx);
        asm volatile("cp.async.commit_group;" ::: "memory");

        if (kt == NQ_IT) {
            // q-part complete: apply per-output-column alpha to accumulators
            #pragma unroll
            for (int j2 = 0; j2 < 8; j2++) {
                const int nc = n0 + wn * 64 + j2 * 8 + 2 * tq;
                const float s0 = alpha[nc], s1 = alpha[nc + 1];
                #pragma unroll
                for (int i = 0; i < 4; i++) {
                    acc[i][j2][0] *= s0; acc[i][j2][1] *= s1;
                    acc[i][j2][2] *= s0; acc[i][j2][3] *= s1;
                }
            }
        }
        compute_stage(kt & (STAGES - 1));
    }

    // ---- epilogue: bias + float2 stores ----
    const int qid = lid >> 2;
    #pragma unroll
    for (int i = 0; i < 4; i++) {
        const int mrow = m0 + wm * 64 + i * 16 + qid;
        #pragma unroll
        for (int j2 = 0; j2 < 8; j2++) {
            const int nc = n0 + wn * 64 + j2 * 8 + 2 * tq;
            const float b0 = bias[nc], b1 = bias[nc + 1];
            float2 v0 = make_float2(acc[i][j2][0] + b0, acc[i][j2][1] + b1);
            float2 v1 = make_float2(acc[i][j2][2] + b0, acc[i][j2][3] + b1);
            *(float2*)&C[(size_t)mrow * N_DIM + nc]       = v0;
            *(float2*)&C[(size_t)(mrow + 8) * N_DIM + nc] = v1;
        }
    }
}

// ---------------------------------------------------------------------------
// Launch. Inputs: input, q_weight, fp_weight, alpha_scale, bias, inv_col_perm.
// ---------------------------------------------------------------------------
extern "C" void kernel_launch(void* const* d_in, const int* in_sizes, int n_in,
                              void* d_out, int out_size) {
    const float* input = (const float*)d_in[0];
    const float* qw    = (const float*)d_in[1];
    const float* fw    = (const float*)d_in[2];
    const float* alpha = (const float*)d_in[3];
    const float* bias  = (const float*)d_in[4];
    const int*   invp  = (const int*)  d_in[5];
    float* out = (float*)d_out;

    perm_conv_A_kernel<<<M_ROWS, 256>>>(input, invp);
    prep_Q_kernel<<<(N_DIM * KQ_DIM) / 256, 256>>>(qw);
    prep_FP_kernel<<<(N_DIM * N_OUTL) / 256, 256>>>(fw);

    static bool attr_set = false;
    if (!attr_set) {
        cudaFuncSetAttribute(gemm_hmma_kernel,
                             cudaFuncAttributeMaxDynamicSharedMemorySize, SMEM_TOTAL);
        attr_set = true;
    }
    dim3 grid(N_DIM / TN, M_ROWS / TM);   // (32, 32)
    gemm_hmma_kernel<<<grid, 256, SMEM_TOTAL>>>(alpha, bias, out);
}